// round 10
// baseline (speedup 1.0000x reference)
#include <cuda_runtime.h>
#include <cuda_fp16.h>
#include <math.h>
#include <stdint.h>

// Problem constants
#define RN   1024
#define CCH  384
#define NCLS 21
#define DFEAT 18816        // 384*7*7
#define HID  1024
#define BETA (1.0f/9.0f)

// GEMM tiling (single fp16 mma path)
#define BM 128
#define BN 64
#define BK 64
#define NST 3
#define ASTRIDE 72
#define A_ELEMS (BM*ASTRIDE)
#define B_ELEMS (BN*ASTRIDE)
#define STAGE_ELEMS (A_ELEMS + B_ELEMS)
#define GSMEM_BYTES (NST*STAGE_ELEMS*2)
#define NSPLIT 2

// ---------------- scratch (device globals; no allocation allowed) ----------------
__device__ __align__(16) __half g_X  [RN * DFEAT];
__device__ __align__(16) __half g_W6 [HID * DFEAT];   // [N,K] fp16
__device__ __align__(16) __half g_W7 [HID * HID];
__device__ __align__(16) __half g_H1 [RN * HID];
__device__ __align__(16) float g_wbT [NCLS * 4 * HID]; // w_bbox transposed [84,1024]
__device__ __align__(16) float g_part[NSPLIT * RN * HID];
__device__ float g_H2[RN * HID];
__device__ float g_cls[RN];
__device__ float g_box[RN];

// ---------------- PTX helpers ------------------------------------------------------
__device__ __forceinline__ uint32_t smem_u32(const void* p) {
    uint32_t a;
    asm("{ .reg .u64 t; cvta.to.shared.u64 t, %1; cvt.u32.u64 %0, t; }" : "=r"(a) : "l"(p));
    return a;
}
__device__ __forceinline__ void cp16(void* sdst, const void* gsrc) {
    uint32_t d = smem_u32(sdst);
    asm volatile("cp.async.cg.shared.global [%0], [%1], 16;" :: "r"(d), "l"(gsrc) : "memory");
}
__device__ __forceinline__ void cp_commit() {
    asm volatile("cp.async.commit_group;" ::: "memory");
}
template <int N>
__device__ __forceinline__ void cp_wait() {
    asm volatile("cp.async.wait_group %0;" :: "n"(N) : "memory");
}
__device__ __forceinline__ void ldsm4(uint32_t* r, uint32_t addr) {
    asm volatile("ldmatrix.sync.aligned.m8n8.x4.shared.b16 {%0,%1,%2,%3}, [%4];"
                 : "=r"(r[0]), "=r"(r[1]), "=r"(r[2]), "=r"(r[3]) : "r"(addr));
}
__device__ __forceinline__ void mma16816(float* c, const uint32_t* a, const uint32_t* b) {
    asm volatile("mma.sync.aligned.m16n8k16.row.col.f32.f16.f16.f32 "
                 "{%0,%1,%2,%3}, {%4,%5,%6,%7}, {%8,%9}, {%0,%1,%2,%3};"
                 : "+f"(c[0]), "+f"(c[1]), "+f"(c[2]), "+f"(c[3])
                 : "r"(a[0]), "r"(a[1]), "r"(a[2]), "r"(a[3]), "r"(b[0]), "r"(b[1]));
}

// ---------------- ROIAlign: factorized offsets/weights, hoisted per-bin ------------
// 392 threads = 49 bins x 8 channel groups; each thread does 48 channels.
__global__ void roi_align_kernel(const float* __restrict__ p2, const float* __restrict__ p3,
                                 const float* __restrict__ p4, const float* __restrict__ p5,
                                 const float* __restrict__ rois, const int* __restrict__ batch_idx)
{
    __shared__ int   sy0[14], sy1[14], sx0[14], sx1[14];   // y premultiplied by S
    __shared__ float swyh[14], swyl[14], swxh[14], swxl[14];

    int r = blockIdx.x;
    float x1 = rois[r*4+0], y1 = rois[r*4+1], x2 = rois[r*4+2], y2 = rois[r*4+3];
    float area = (x2 - x1) * (y2 - y1);
    float lf = floorf(4.0f + log2f(sqrtf(area) / 224.0f + 1e-6f));
    lf = fminf(fmaxf(lf, 2.0f), 5.0f);
    int lvl = (int)lf - 2;
    int S = 56 >> lvl;
    float scale = 0.25f / (float)(1 << lvl);
    const float* feat = (lvl == 0) ? p2 : (lvl == 1) ? p3 : (lvl == 2) ? p4 : p5;
    const float* img0 = feat + (size_t)batch_idx[r] * CCH * S * S;

    float x1s = x1 * scale, y1s = y1 * scale;
    float rw = fmaxf(x2 * scale - x1s, 1.0f);
    float rh = fmaxf(y2 * scale - y1s, 1.0f);

    int t = threadIdx.x;
    if (t < 14) {
        float kk = ((float)t + 0.5f) * 0.5f;
        // x entry (validity folded, 0.5 factor so wy*wx carries the 0.25 mean)
        float xs = x1s + (rw / 7.0f) * kk;
        float vx = (xs >= -1.0f && xs <= (float)S) ? 0.5f : 0.0f;
        float x = fminf(fmaxf(xs, 0.0f), (float)(S - 1));
        float x0f = floorf(x);
        float lx = x - x0f;
        int x0 = (int)x0f;
        sx0[t] = x0;
        sx1[t] = min(x0 + 1, S - 1);
        swxh[t] = vx * (1.0f - lx);
        swxl[t] = vx * lx;
        // y entry (row offsets premultiplied by S)
        float ys = y1s + (rh / 7.0f) * kk;
        float vy = (ys >= -1.0f && ys <= (float)S) ? 0.5f : 0.0f;
        float y = fminf(fmaxf(ys, 0.0f), (float)(S - 1));
        float y0f = floorf(y);
        float ly = y - y0f;
        int y0 = (int)y0f;
        sy0[t] = y0 * S;
        sy1[t] = min(y0 + 1, S - 1) * S;
        swyh[t] = vy * (1.0f - ly);
        swyl[t] = vy * ly;
    }
    __syncthreads();

    int bin = t % 49, cg = t / 49;       // cg 0..7
    int ph = bin / 7, pw = bin - ph * 7;
    int iy = 2 * ph, ix = 2 * pw;

    int   rowo[4] = { sy0[iy], sy1[iy], sy0[iy+1], sy1[iy+1] };
    int   colo[4] = { sx0[ix], sx1[ix], sx0[ix+1], sx1[ix+1] };
    float wy[4]   = { swyh[iy], swyl[iy], swyh[iy+1], swyl[iy+1] };
    float wx[4]   = { swxh[ix], swxl[ix], swxh[ix+1], swxl[ix+1] };

    int off[16]; float w[16];
    #pragma unroll
    for (int i = 0; i < 4; i++)
        #pragma unroll
        for (int j = 0; j < 4; j++) {
            off[i*4+j] = rowo[i] + colo[j];
            w[i*4+j]   = wy[i] * wx[j];
        }

    size_t rbase = (size_t)r * DFEAT;
    size_t cstep = (size_t)S * S;
    const float* img = img0 + (size_t)cg * cstep;
    size_t oidx = rbase + (size_t)cg * 49 + bin;
    #pragma unroll 2
    for (int c = cg; c < CCH; c += 8) {
        float acc = 0.0f;
        #pragma unroll
        for (int k = 0; k < 16; k++) acc += w[k] * __ldg(img + off[k]);
        g_X[oidx] = __float2half(acc);
        img += 8 * cstep;
        oidx += 8 * 49;
    }
}

// ---------------- transpose to fp16: W[K,N] -> T[N,K] -----------------------------
__global__ void transpose_h(const float* __restrict__ W, __half* __restrict__ T,
                            int K, int N)
{
    __shared__ float tile[32][33];
    int k0 = blockIdx.x * 32, n0 = blockIdx.y * 32;
    int tx = threadIdx.x, ty = threadIdx.y;
    #pragma unroll
    for (int i = 0; i < 4; i++)
        tile[ty + i*8][tx] = W[(size_t)(k0 + ty + i*8) * N + n0 + tx];
    __syncthreads();
    #pragma unroll
    for (int i = 0; i < 4; i++) {
        int n = n0 + ty + i*8;
        int k = k0 + tx;
        T[(size_t)n * K + k] = __float2half(tile[tx][ty + i*8]);
    }
}

// ---------------- w_bbox transpose fp32: wb[1024,84] -> g_wbT[84,1024] ------------
__global__ void transpose_b(const float* __restrict__ wb)
{
    __shared__ float tile[32][33];
    int b = blockIdx.x;                          // 0..95
    int k0 = (b % 32) * 32, c0 = (b / 32) * 32;  // c0 in {0,32,64}
    int tx = threadIdx.x, ty = threadIdx.y;
    #pragma unroll
    for (int i = 0; i < 4; i++) {
        int c = c0 + tx;
        tile[ty + i*8][tx] = (c < NCLS*4) ? wb[(size_t)(k0 + ty + i*8) * (NCLS*4) + c] : 0.0f;
    }
    __syncthreads();
    #pragma unroll
    for (int i = 0; i < 4; i++) {
        int c = c0 + ty + i*8;
        if (c < NCLS*4) g_wbT[(size_t)c * HID + k0 + tx] = tile[tx][ty + i*8];
    }
}

// ---------------- fp16 GEMM on mma.sync (HMMA), split-K, 3-stage -------------------
__global__ __launch_bounds__(256, 2)
void gemmh(const __half* __restrict__ A, const __half* __restrict__ B,
           float* __restrict__ part, int K, int kLen)
{
    extern __shared__ __half sm[];
    int tid = threadIdx.x, wid = tid >> 5, lane = tid & 31;
    int bm = blockIdx.y * BM, bn = blockIdx.x * BN;
    int kOff = blockIdx.z * kLen;
    float* pout = part + (size_t)blockIdx.z * RN * HID;
    int wm = (wid & 3) * 32;
    int wn = (wid >> 2) * 32;

    float acc[2][4][4];
    #pragma unroll
    for (int mt = 0; mt < 2; mt++)
        #pragma unroll
        for (int nt = 0; nt < 4; nt++)
            #pragma unroll
            for (int i = 0; i < 4; i++) acc[mt][nt][i] = 0.0f;

    int nc = kLen / BK;

    auto load_stage = [&](int c, int s) {
        __half* st = sm + s * STAGE_ELEMS;
        int k0 = kOff + c * BK;
        #pragma unroll
        for (int j = 0; j < 4; j++) {
            int i = tid + j * 256;
            int row = i >> 3, seg = i & 7;
            cp16(&st[row * ASTRIDE + seg * 8], &A[(size_t)(bm + row) * K + k0 + seg * 8]);
        }
        #pragma unroll
        for (int j = 0; j < 2; j++) {
            int i = tid + j * 256;
            int row = i >> 3, seg = i & 7;
            cp16(&st[A_ELEMS + row * ASTRIDE + seg * 8], &B[(size_t)(bn + row) * K + k0 + seg * 8]);
        }
        cp_commit();
    };

    load_stage(0, 0);
    load_stage(1, 1);

    for (int c = 0; c < nc; c++) {
        if (c + 1 < nc) cp_wait<1>(); else cp_wait<0>();
        __syncthreads();
        if (c + 2 < nc) load_stage(c + 2, (c + 2) % NST);

        __half* st = sm + (c % NST) * STAGE_ELEMS;
        uint32_t sA = smem_u32(st);
        #pragma unroll
        for (int ks = 0; ks < 4; ks++) {
            int kc = ks * 16;
            uint32_t ah[2][4], bb[4][2];
            #pragma unroll
            for (int mt = 0; mt < 2; mt++) {
                int row = wm + mt * 16 + (lane & 15);
                int col = kc + ((lane >> 4) << 3);
                ldsm4(ah[mt], sA + (uint32_t)(row * ASTRIDE + col) * 2);
            }
            #pragma unroll
            for (int p = 0; p < 2; p++) {
                int rown = wn + p * 16 + ((lane & 16) >> 1) + (lane & 7);
                int col = kc + (lane & 8);
                uint32_t r4[4];
                ldsm4(r4, sA + A_ELEMS * 2 + (uint32_t)(rown * ASTRIDE + col) * 2);
                bb[2*p][0] = r4[0]; bb[2*p][1] = r4[1];
                bb[2*p+1][0] = r4[2]; bb[2*p+1][1] = r4[3];
            }
            #pragma unroll
            for (int mt = 0; mt < 2; mt++)
                #pragma unroll
                for (int nt = 0; nt < 4; nt++)
                    mma16816(acc[mt][nt], ah[mt], bb[nt]);
        }
    }

    int lrow = lane >> 2, lcol = (lane & 3) * 2;
    #pragma unroll
    for (int mt = 0; mt < 2; mt++) {
        #pragma unroll
        for (int nt = 0; nt < 4; nt++) {
            int col = bn + wn + nt * 8 + lcol;
            #pragma unroll
            for (int half = 0; half < 2; half++) {
                int row = bm + wm + mt * 16 + lrow + half * 8;
                float2 v;
                v.x = acc[mt][nt][half * 2 + 0];
                v.y = acc[mt][nt][half * 2 + 1];
                *(float2*)&pout[(size_t)row * HID + col] = v;
            }
        }
    }
}

// ---------------- combine split-K partials + bias + relu --------------------------
__global__ void combine_kernel(const float* __restrict__ part, const float* __restrict__ bias,
                               float* __restrict__ outf, __half* __restrict__ Oh, int mode)
{
    int idx = blockIdx.x * blockDim.x + threadIdx.x;
    int col = idx & (HID - 1);
    float v = part[idx] + part[RN * HID + idx] + bias[col];
    v = fmaxf(v, 0.0f);
    if (mode == 0) outf[idx] = v;
    else           Oh[idx] = __float2half(v);
}

// ---------------- head: smem-staged w_cls, coalesced wbT, per-roi losses ----------
__global__ void head_loss_kernel(const float* __restrict__ H2,
                                 const float* __restrict__ w_cls, const float* __restrict__ b_cls,
                                 const float* __restrict__ b_bbox,
                                 const int* __restrict__ labels, const float* __restrict__ regt)
{
    extern __shared__ float swc[];      // [1024*21]
    int t = threadIdx.x, warp = t >> 5, lane = t & 31;
    for (int i = t; i < HID * NCLS; i += 256) swc[i] = w_cls[i];
    __syncthreads();

    #pragma unroll
    for (int q = 0; q < 2; q++) {
        int r = blockIdx.x * 16 + warp * 2 + q;
        int label = labels[r];

        float x[32];
        #pragma unroll
        for (int i = 0; i < 32; i++) x[i] = H2[(size_t)r * HID + lane + 32 * i];

        float lg[NCLS];
        #pragma unroll
        for (int j = 0; j < NCLS; j++) {
            float s = 0.0f;
            #pragma unroll
            for (int i = 0; i < 32; i++) s += x[i] * swc[(lane + 32 * i) * NCLS + j];
            #pragma unroll
            for (int o = 16; o > 0; o >>= 1) s += __shfl_xor_sync(0xffffffffu, s, o);
            lg[j] = s + b_cls[j];
        }

        float sel[4];
        #pragma unroll
        for (int i4 = 0; i4 < 4; i4++) {
            const float* wrow = g_wbT + (size_t)(label * 4 + i4) * HID;
            float s = 0.0f;
            #pragma unroll
            for (int i = 0; i < 32; i++) s += x[i] * wrow[lane + 32 * i];
            #pragma unroll
            for (int o = 16; o > 0; o >>= 1) s += __shfl_xor_sync(0xffffffffu, s, o);
            sel[i4] = s + b_bbox[label * 4 + i4];
        }

        if (lane == 0) {
            float m = -1e30f;
            #pragma unroll
            for (int j = 0; j < NCLS; j++) m = fmaxf(m, lg[j]);
            float se = 0.0f;
            #pragma unroll
            for (int j = 0; j < NCLS; j++) se += expf(lg[j] - m);
            float ce = logf(se) + m - lg[label];
            float pt = expf(-ce);
            float fw = (1.0f - pt) * (1.0f - pt);
            float aw = (label > 0) ? 0.25f : 0.75f;
            g_cls[r] = fw * aw * ce;

            float bl = 0.0f;
            #pragma unroll
            for (int i4 = 0; i4 < 4; i4++) {
                float d = sel[i4] - regt[r * 4 + i4];
                float ad = fabsf(d);
                bl += (ad < BETA) ? 0.5f * d * d / BETA : ad - 0.5f * BETA;
            }
            g_box[r] = (label > 0) ? bl : 0.0f;
        }
    }
}

// ---------------- deterministic final reduction -----------------------------------
__global__ void reduce_kernel(float* __restrict__ out)
{
    __shared__ float s1[RN];
    __shared__ float s2[RN];
    int t = threadIdx.x;
    s1[t] = g_cls[t];
    s2[t] = g_box[t];
    __syncthreads();
    for (int o = RN / 2; o > 0; o >>= 1) {
        if (t < o) { s1[t] += s1[t + o]; s2[t] += s2[t + o]; }
        __syncthreads();
    }
    if (t == 0) {
        out[0] = s1[0] / (float)RN;
        out[1] = s2[0] / (float)RN;
    }
}

// ---------------- launch ----------------------------------------------------------
extern "C" void kernel_launch(void* const* d_in, const int* in_sizes, int n_in,
                              void* d_out, int out_size)
{
    const float* p2     = (const float*)d_in[0];
    const float* p3     = (const float*)d_in[1];
    const float* p4     = (const float*)d_in[2];
    const float* p5     = (const float*)d_in[3];
    const float* rois   = (const float*)d_in[4];
    const int*   bidx   = (const int*)  d_in[5];
    const int*   labels = (const int*)  d_in[6];
    const float* regt   = (const float*)d_in[7];
    const float* w_fc6  = (const float*)d_in[8];
    const float* b_fc6  = (const float*)d_in[9];
    const float* w_fc7  = (const float*)d_in[10];
    const float* b_fc7  = (const float*)d_in[11];
    const float* w_cls  = (const float*)d_in[12];
    const float* b_cls  = (const float*)d_in[13];
    const float* w_bbox = (const float*)d_in[14];
    const float* b_bbox = (const float*)d_in[15];

    __half *Xp, *W6p, *W7p, *H1p;
    float *H2p, *Pp;
    cudaGetSymbolAddress((void**)&Xp,  g_X);
    cudaGetSymbolAddress((void**)&W6p, g_W6);
    cudaGetSymbolAddress((void**)&W7p, g_W7);
    cudaGetSymbolAddress((void**)&H1p, g_H1);
    cudaGetSymbolAddress((void**)&H2p, g_H2);
    cudaGetSymbolAddress((void**)&Pp,  g_part);

    cudaFuncSetAttribute(gemmh, cudaFuncAttributeMaxDynamicSharedMemorySize, GSMEM_BYTES);
    cudaFuncSetAttribute(head_loss_kernel, cudaFuncAttributeMaxDynamicSharedMemorySize,
                         HID * NCLS * (int)sizeof(float));

    // 1) weight transposes first (streaming traffic done before roi's L2 window)
    transpose_h<<<dim3(DFEAT / 32, HID / 32), dim3(32, 8)>>>(w_fc6, W6p, DFEAT, HID);
    transpose_h<<<dim3(HID / 32, HID / 32),   dim3(32, 8)>>>(w_fc7, W7p, HID, HID);
    transpose_b<<<96, dim3(32, 8)>>>(w_bbox);

    // 2) ROIAlign + flatten -> g_X fp16 [1024, 18816]
    roi_align_kernel<<<RN, 392>>>(p2, p3, p4, p5, rois, bidx);

    // 3) fc6 split-K=2 -> combine -> H1 fp16
    dim3 grid(HID / BN, RN / BM, NSPLIT);
    gemmh<<<grid, 256, GSMEM_BYTES>>>(Xp, W6p, Pp, DFEAT, DFEAT / NSPLIT);
    combine_kernel<<<RN * HID / 256, 256>>>(Pp, b_fc6, nullptr, H1p, 1);

    // 4) fc7 split-K=2 -> H2 fp32
    gemmh<<<grid, 256, GSMEM_BYTES>>>(H1p, W7p, Pp, HID, HID / NSPLIT);
    combine_kernel<<<RN * HID / 256, 256>>>(Pp, b_fc7, H2p, nullptr, 0);

    // 5) heads + per-roi losses
    head_loss_kernel<<<64, 256, HID * NCLS * sizeof(float)>>>(H2p, w_cls, b_cls,
                                                              b_bbox, labels, regt);

    // 6) deterministic reduction -> out[0..1]
    reduce_kernel<<<1, RN>>>((float*)d_out);
}

// round 12
// speedup vs baseline: 1.1092x; 1.1092x over previous
#include <cuda_runtime.h>
#include <cuda_fp16.h>
#include <math.h>
#include <stdint.h>

// Problem constants
#define RN   1024
#define CCH  384
#define NCLS 21
#define DFEAT 18816        // 384*7*7
#define HID  1024
#define BETA (1.0f/9.0f)

// GEMM tiling (single fp16 mma path)
#define BM 128
#define BN 64
#define BK 64
#define NST 3
#define ASTRIDE 72
#define A_ELEMS (BM*ASTRIDE)
#define B_ELEMS (BN*ASTRIDE)
#define STAGE_ELEMS (A_ELEMS + B_ELEMS)
#define GSMEM_BYTES (NST*STAGE_ELEMS*2)
#define NSPLIT 2

// ---------------- scratch (device globals; no allocation allowed) ----------------
__device__ __align__(16) __half g_X  [RN * DFEAT];
__device__ __align__(16) __half g_W6 [HID * DFEAT];   // [N,K] fp16
__device__ __align__(16) __half g_W7 [HID * HID];
__device__ __align__(16) __half g_H1 [RN * HID];
__device__ __align__(16) float g_wbT [NCLS * 4 * HID]; // w_bbox transposed [84,1024]
__device__ __align__(16) float g_part[NSPLIT * RN * HID];
__device__ float g_H2[RN * HID];
__device__ float g_cls[RN];
__device__ float g_box[RN];

// ---------------- PTX helpers ------------------------------------------------------
__device__ __forceinline__ uint32_t smem_u32(const void* p) {
    uint32_t a;
    asm("{ .reg .u64 t; cvta.to.shared.u64 t, %1; cvt.u32.u64 %0, t; }" : "=r"(a) : "l"(p));
    return a;
}
__device__ __forceinline__ void cp16(void* sdst, const void* gsrc) {
    uint32_t d = smem_u32(sdst);
    asm volatile("cp.async.cg.shared.global [%0], [%1], 16;" :: "r"(d), "l"(gsrc) : "memory");
}
__device__ __forceinline__ void cp_commit() {
    asm volatile("cp.async.commit_group;" ::: "memory");
}
template <int N>
__device__ __forceinline__ void cp_wait() {
    asm volatile("cp.async.wait_group %0;" :: "n"(N) : "memory");
}
__device__ __forceinline__ void ldsm4(uint32_t* r, uint32_t addr) {
    asm volatile("ldmatrix.sync.aligned.m8n8.x4.shared.b16 {%0,%1,%2,%3}, [%4];"
                 : "=r"(r[0]), "=r"(r[1]), "=r"(r[2]), "=r"(r[3]) : "r"(addr));
}
__device__ __forceinline__ void mma16816(float* c, const uint32_t* a, const uint32_t* b) {
    asm volatile("mma.sync.aligned.m16n8k16.row.col.f32.f16.f16.f32 "
                 "{%0,%1,%2,%3}, {%4,%5,%6,%7}, {%8,%9}, {%0,%1,%2,%3};"
                 : "+f"(c[0]), "+f"(c[1]), "+f"(c[2]), "+f"(c[3])
                 : "r"(a[0]), "r"(a[1]), "r"(a[2]), "r"(a[3]), "r"(b[0]), "r"(b[1]));
}

// ---------------- ROIAlign: bin-fixed threads, minimal hoisted state ---------------
// 512 threads, t<490 active: bin = t%49 (fixed), channel = t/49 + 10*i.
// Validity + 0.25 sample-mean folded into the per-axis weights (0.5 each axis).
__global__ void __launch_bounds__(512, 2)
roi_align_kernel(const float* __restrict__ p2, const float* __restrict__ p3,
                 const float* __restrict__ p4, const float* __restrict__ p5,
                 const float* __restrict__ rois, const int* __restrict__ batch_idx)
{
    __shared__ int   sy0[14], sy1[14], sx0[14], sx1[14];   // y offsets premultiplied by S
    __shared__ float swyh[14], swyl[14], swxh[14], swxl[14];

    int r = blockIdx.x;
    float x1 = rois[r*4+0], y1 = rois[r*4+1], x2 = rois[r*4+2], y2 = rois[r*4+3];
    float area = (x2 - x1) * (y2 - y1);
    float lf = floorf(4.0f + log2f(sqrtf(area) / 224.0f + 1e-6f));
    lf = fminf(fmaxf(lf, 2.0f), 5.0f);
    int lvl = (int)lf - 2;
    int S = 56 >> lvl;
    float scale = 0.25f / (float)(1 << lvl);
    const float* feat = (lvl == 0) ? p2 : (lvl == 1) ? p3 : (lvl == 2) ? p4 : p5;
    const float* img0 = feat + (size_t)batch_idx[r] * CCH * S * S;

    float x1s = x1 * scale, y1s = y1 * scale;
    float rw = fmaxf(x2 * scale - x1s, 1.0f);
    float rh = fmaxf(y2 * scale - y1s, 1.0f);

    int t = threadIdx.x;
    if (t < 14) {
        float kk = ((float)t + 0.5f) * 0.5f;
        float xs = x1s + (rw / 7.0f) * kk;
        float vx = (xs >= -1.0f && xs <= (float)S) ? 0.5f : 0.0f;
        float x = fminf(fmaxf(xs, 0.0f), (float)(S - 1));
        float x0f = floorf(x);
        float lx = x - x0f;
        int x0 = (int)x0f;
        sx0[t] = x0;
        sx1[t] = min(x0 + 1, S - 1);
        swxh[t] = vx * (1.0f - lx);
        swxl[t] = vx * lx;

        float ys = y1s + (rh / 7.0f) * kk;
        float vy = (ys >= -1.0f && ys <= (float)S) ? 0.5f : 0.0f;
        float y = fminf(fmaxf(ys, 0.0f), (float)(S - 1));
        float y0f = floorf(y);
        float ly = y - y0f;
        int y0 = (int)y0f;
        sy0[t] = y0 * S;
        sy1[t] = min(y0 + 1, S - 1) * S;
        swyh[t] = vy * (1.0f - ly);
        swyl[t] = vy * ly;
    }
    __syncthreads();

    if (t >= 490) return;
    int cg  = t / 49;
    int bin = t - cg * 49;
    int ph = bin / 7, pw = bin - ph * 7;
    int iy = 2 * ph, ix = 2 * pw;

    // hoisted per-bin state: 8 offsets + 8 weights (products computed in-loop)
    int   ro0 = sy0[iy],   ro1 = sy1[iy],   ro2 = sy0[iy+1], ro3 = sy1[iy+1];
    int   co0 = sx0[ix],   co1 = sx1[ix],   co2 = sx0[ix+1], co3 = sx1[ix+1];
    float wy0 = swyh[iy],  wy1 = swyl[iy],  wy2 = swyh[iy+1], wy3 = swyl[iy+1];
    float wx0 = swxh[ix],  wx1 = swxl[ix],  wx2 = swxh[ix+1], wx3 = swxl[ix+1];

    size_t cstep = (size_t)S * S;
    const float* img = img0 + (size_t)cg * cstep;
    __half* out = g_X + (size_t)r * DFEAT + (size_t)cg * 49 + bin;

    for (int c = cg; c < CCH; c += 10) {
        const float* r0 = img + ro0;
        const float* r1 = img + ro1;
        const float* r2 = img + ro2;
        const float* r3 = img + ro3;
        float acc = wy0 * (wx0 * r0[co0] + wx1 * r0[co1] + wx2 * r0[co2] + wx3 * r0[co3])
                  + wy1 * (wx0 * r1[co0] + wx1 * r1[co1] + wx2 * r1[co2] + wx3 * r1[co3])
                  + wy2 * (wx0 * r2[co0] + wx1 * r2[co1] + wx2 * r2[co2] + wx3 * r2[co3])
                  + wy3 * (wx0 * r3[co0] + wx1 * r3[co1] + wx2 * r3[co2] + wx3 * r3[co3]);
        *out = __float2half(acc);
        img += 10 * cstep;
        out += 10 * 49;
    }
}

// ---------------- transpose to fp16: W[K,N] -> T[N,K] -----------------------------
__global__ void transpose_h(const float* __restrict__ W, __half* __restrict__ T,
                            int K, int N)
{
    __shared__ float tile[32][33];
    int k0 = blockIdx.x * 32, n0 = blockIdx.y * 32;
    int tx = threadIdx.x, ty = threadIdx.y;
    #pragma unroll
    for (int i = 0; i < 4; i++)
        tile[ty + i*8][tx] = W[(size_t)(k0 + ty + i*8) * N + n0 + tx];
    __syncthreads();
    #pragma unroll
    for (int i = 0; i < 4; i++) {
        int n = n0 + ty + i*8;
        int k = k0 + tx;
        T[(size_t)n * K + k] = __float2half(tile[tx][ty + i*8]);
    }
}

// ---------------- w_bbox transpose fp32: wb[1024,84] -> g_wbT[84,1024] ------------
__global__ void transpose_b(const float* __restrict__ wb)
{
    __shared__ float tile[32][33];
    int b = blockIdx.x;                          // 0..95
    int k0 = (b % 32) * 32, c0 = (b / 32) * 32;  // c0 in {0,32,64}
    int tx = threadIdx.x, ty = threadIdx.y;
    #pragma unroll
    for (int i = 0; i < 4; i++) {
        int c = c0 + tx;
        tile[ty + i*8][tx] = (c < NCLS*4) ? wb[(size_t)(k0 + ty + i*8) * (NCLS*4) + c] : 0.0f;
    }
    __syncthreads();
    #pragma unroll
    for (int i = 0; i < 4; i++) {
        int c = c0 + ty + i*8;
        if (c < NCLS*4) g_wbT[(size_t)c * HID + k0 + tx] = tile[tx][ty + i*8];
    }
}

// ---------------- fp16 GEMM on mma.sync (HMMA), split-K, 3-stage -------------------
__global__ __launch_bounds__(256, 2)
void gemmh(const __half* __restrict__ A, const __half* __restrict__ B,
           float* __restrict__ part, int K, int kLen)
{
    extern __shared__ __half sm[];
    int tid = threadIdx.x, wid = tid >> 5, lane = tid & 31;
    int bm = blockIdx.y * BM, bn = blockIdx.x * BN;
    int kOff = blockIdx.z * kLen;
    float* pout = part + (size_t)blockIdx.z * RN * HID;
    int wm = (wid & 3) * 32;
    int wn = (wid >> 2) * 32;

    float acc[2][4][4];
    #pragma unroll
    for (int mt = 0; mt < 2; mt++)
        #pragma unroll
        for (int nt = 0; nt < 4; nt++)
            #pragma unroll
            for (int i = 0; i < 4; i++) acc[mt][nt][i] = 0.0f;

    int nc = kLen / BK;

    auto load_stage = [&](int c, int s) {
        __half* st = sm + s * STAGE_ELEMS;
        int k0 = kOff + c * BK;
        #pragma unroll
        for (int j = 0; j < 4; j++) {
            int i = tid + j * 256;
            int row = i >> 3, seg = i & 7;
            cp16(&st[row * ASTRIDE + seg * 8], &A[(size_t)(bm + row) * K + k0 + seg * 8]);
        }
        #pragma unroll
        for (int j = 0; j < 2; j++) {
            int i = tid + j * 256;
            int row = i >> 3, seg = i & 7;
            cp16(&st[A_ELEMS + row * ASTRIDE + seg * 8], &B[(size_t)(bn + row) * K + k0 + seg * 8]);
        }
        cp_commit();
    };

    load_stage(0, 0);
    load_stage(1, 1);

    for (int c = 0; c < nc; c++) {
        if (c + 1 < nc) cp_wait<1>(); else cp_wait<0>();
        __syncthreads();
        if (c + 2 < nc) load_stage(c + 2, (c + 2) % NST);

        __half* st = sm + (c % NST) * STAGE_ELEMS;
        uint32_t sA = smem_u32(st);
        #pragma unroll
        for (int ks = 0; ks < 4; ks++) {
            int kc = ks * 16;
            uint32_t ah[2][4], bb[4][2];
            #pragma unroll
            for (int mt = 0; mt < 2; mt++) {
                int row = wm + mt * 16 + (lane & 15);
                int col = kc + ((lane >> 4) << 3);
                ldsm4(ah[mt], sA + (uint32_t)(row * ASTRIDE + col) * 2);
            }
            #pragma unroll
            for (int p = 0; p < 2; p++) {
                int rown = wn + p * 16 + ((lane & 16) >> 1) + (lane & 7);
                int col = kc + (lane & 8);
                uint32_t r4[4];
                ldsm4(r4, sA + A_ELEMS * 2 + (uint32_t)(rown * ASTRIDE + col) * 2);
                bb[2*p][0] = r4[0]; bb[2*p][1] = r4[1];
                bb[2*p+1][0] = r4[2]; bb[2*p+1][1] = r4[3];
            }
            #pragma unroll
            for (int mt = 0; mt < 2; mt++)
                #pragma unroll
                for (int nt = 0; nt < 4; nt++)
                    mma16816(acc[mt][nt], ah[mt], bb[nt]);
        }
    }

    int lrow = lane >> 2, lcol = (lane & 3) * 2;
    #pragma unroll
    for (int mt = 0; mt < 2; mt++) {
        #pragma unroll
        for (int nt = 0; nt < 4; nt++) {
            int col = bn + wn + nt * 8 + lcol;
            #pragma unroll
            for (int half = 0; half < 2; half++) {
                int row = bm + wm + mt * 16 + lrow + half * 8;
                float2 v;
                v.x = acc[mt][nt][half * 2 + 0];
                v.y = acc[mt][nt][half * 2 + 1];
                *(float2*)&pout[(size_t)row * HID + col] = v;
            }
        }
    }
}

// ---------------- combine split-K partials + bias + relu --------------------------
__global__ void combine_kernel(const float* __restrict__ part, const float* __restrict__ bias,
                               float* __restrict__ outf, __half* __restrict__ Oh, int mode)
{
    int idx = blockIdx.x * blockDim.x + threadIdx.x;
    int col = idx & (HID - 1);
    float v = part[idx] + part[RN * HID + idx] + bias[col];
    v = fmaxf(v, 0.0f);
    if (mode == 0) outf[idx] = v;
    else           Oh[idx] = __float2half(v);
}

// ---------------- head: smem-staged w_cls, coalesced wbT, per-roi losses ----------
__global__ void head_loss_kernel(const float* __restrict__ H2,
                                 const float* __restrict__ w_cls, const float* __restrict__ b_cls,
                                 const float* __restrict__ b_bbox,
                                 const int* __restrict__ labels, const float* __restrict__ regt)
{
    extern __shared__ float swc[];      // [1024*21]
    int t = threadIdx.x, warp = t >> 5, lane = t & 31;
    for (int i = t; i < HID * NCLS; i += 256) swc[i] = w_cls[i];
    __syncthreads();

    #pragma unroll
    for (int q = 0; q < 2; q++) {
        int r = blockIdx.x * 16 + warp * 2 + q;
        int label = labels[r];

        float x[32];
        #pragma unroll
        for (int i = 0; i < 32; i++) x[i] = H2[(size_t)r * HID + lane + 32 * i];

        float lg[NCLS];
        #pragma unroll
        for (int j = 0; j < NCLS; j++) {
            float s = 0.0f;
            #pragma unroll
            for (int i = 0; i < 32; i++) s += x[i] * swc[(lane + 32 * i) * NCLS + j];
            #pragma unroll
            for (int o = 16; o > 0; o >>= 1) s += __shfl_xor_sync(0xffffffffu, s, o);
            lg[j] = s + b_cls[j];
        }

        float sel[4];
        #pragma unroll
        for (int i4 = 0; i4 < 4; i4++) {
            const float* wrow = g_wbT + (size_t)(label * 4 + i4) * HID;
            float s = 0.0f;
            #pragma unroll
            for (int i = 0; i < 32; i++) s += x[i] * wrow[lane + 32 * i];
            #pragma unroll
            for (int o = 16; o > 0; o >>= 1) s += __shfl_xor_sync(0xffffffffu, s, o);
            sel[i4] = s + b_bbox[label * 4 + i4];
        }

        if (lane == 0) {
            float m = -1e30f;
            #pragma unroll
            for (int j = 0; j < NCLS; j++) m = fmaxf(m, lg[j]);
            float se = 0.0f;
            #pragma unroll
            for (int j = 0; j < NCLS; j++) se += expf(lg[j] - m);
            float ce = logf(se) + m - lg[label];
            float pt = expf(-ce);
            float fw = (1.0f - pt) * (1.0f - pt);
            float aw = (label > 0) ? 0.25f : 0.75f;
            g_cls[r] = fw * aw * ce;

            float bl = 0.0f;
            #pragma unroll
            for (int i4 = 0; i4 < 4; i4++) {
                float d = sel[i4] - regt[r * 4 + i4];
                float ad = fabsf(d);
                bl += (ad < BETA) ? 0.5f * d * d / BETA : ad - 0.5f * BETA;
            }
            g_box[r] = (label > 0) ? bl : 0.0f;
        }
    }
}

// ---------------- deterministic final reduction -----------------------------------
__global__ void reduce_kernel(float* __restrict__ out)
{
    __shared__ float s1[RN];
    __shared__ float s2[RN];
    int t = threadIdx.x;
    s1[t] = g_cls[t];
    s2[t] = g_box[t];
    __syncthreads();
    for (int o = RN / 2; o > 0; o >>= 1) {
        if (t < o) { s1[t] += s1[t + o]; s2[t] += s2[t + o]; }
        __syncthreads();
    }
    if (t == 0) {
        out[0] = s1[0] / (float)RN;
        out[1] = s2[0] / (float)RN;
    }
}

// ---------------- launch ----------------------------------------------------------
extern "C" void kernel_launch(void* const* d_in, const int* in_sizes, int n_in,
                              void* d_out, int out_size)
{
    const float* p2     = (const float*)d_in[0];
    const float* p3     = (const float*)d_in[1];
    const float* p4     = (const float*)d_in[2];
    const float* p5     = (const float*)d_in[3];
    const float* rois   = (const float*)d_in[4];
    const int*   bidx   = (const int*)  d_in[5];
    const int*   labels = (const int*)  d_in[6];
    const float* regt   = (const float*)d_in[7];
    const float* w_fc6  = (const float*)d_in[8];
    const float* b_fc6  = (const float*)d_in[9];
    const float* w_fc7  = (const float*)d_in[10];
    const float* b_fc7  = (const float*)d_in[11];
    const float* w_cls  = (const float*)d_in[12];
    const float* b_cls  = (const float*)d_in[13];
    const float* w_bbox = (const float*)d_in[14];
    const float* b_bbox = (const float*)d_in[15];

    __half *Xp, *W6p, *W7p, *H1p;
    float *H2p, *Pp;
    cudaGetSymbolAddress((void**)&Xp,  g_X);
    cudaGetSymbolAddress((void**)&W6p, g_W6);
    cudaGetSymbolAddress((void**)&W7p, g_W7);
    cudaGetSymbolAddress((void**)&H1p, g_H1);
    cudaGetSymbolAddress((void**)&H2p, g_H2);
    cudaGetSymbolAddress((void**)&Pp,  g_part);

    cudaFuncSetAttribute(gemmh, cudaFuncAttributeMaxDynamicSharedMemorySize, GSMEM_BYTES);
    cudaFuncSetAttribute(head_loss_kernel, cudaFuncAttributeMaxDynamicSharedMemorySize,
                         HID * NCLS * (int)sizeof(float));

    // 1) weight transposes first (streaming traffic done before roi's L2 window)
    transpose_h<<<dim3(DFEAT / 32, HID / 32), dim3(32, 8)>>>(w_fc6, W6p, DFEAT, HID);
    transpose_h<<<dim3(HID / 32, HID / 32),   dim3(32, 8)>>>(w_fc7, W7p, HID, HID);
    transpose_b<<<96, dim3(32, 8)>>>(w_bbox);

    // 2) ROIAlign + flatten -> g_X fp16 [1024, 18816]
    roi_align_kernel<<<RN, 512>>>(p2, p3, p4, p5, rois, bidx);

    // 3) fc6 split-K=2 -> combine -> H1 fp16
    dim3 grid(HID / BN, RN / BM, NSPLIT);
    gemmh<<<grid, 256, GSMEM_BYTES>>>(Xp, W6p, Pp, DFEAT, DFEAT / NSPLIT);
    combine_kernel<<<RN * HID / 256, 256>>>(Pp, b_fc6, nullptr, H1p, 1);

    // 4) fc7 split-K=2 -> H2 fp32
    gemmh<<<grid, 256, GSMEM_BYTES>>>(H1p, W7p, Pp, HID, HID / NSPLIT);
    combine_kernel<<<RN * HID / 256, 256>>>(Pp, b_fc7, H2p, nullptr, 0);

    // 5) heads + per-roi losses
    head_loss_kernel<<<64, 256, HID * NCLS * sizeof(float)>>>(H2p, w_cls, b_cls,
                                                              b_bbox, labels, regt);

    // 6) deterministic reduction -> out[0..1]
    reduce_kernel<<<1, RN>>>((float*)d_out);
}

// round 13
// speedup vs baseline: 1.2081x; 1.0891x over previous
#include <cuda_runtime.h>
#include <cuda_fp16.h>
#include <math.h>
#include <stdint.h>

// Problem constants
#define RN   1024
#define CCH  384
#define NCLS 21
#define DFEAT 18816        // 384*7*7
#define HID  1024
#define BETA (1.0f/9.0f)

// GEMM tiling (single fp16 mma path)
#define BM 128
#define BN 64
#define BK 64
#define NST 3
#define ASTRIDE 72
#define A_ELEMS (BM*ASTRIDE)
#define B_ELEMS (BN*ASTRIDE)
#define STAGE_ELEMS (A_ELEMS + B_ELEMS)
#define GSMEM_BYTES (NST*STAGE_ELEMS*2)
#define NSPLIT 2

// ---------------- scratch (device globals; no allocation allowed) ----------------
__device__ __align__(16) __half g_X  [RN * DFEAT];
__device__ __align__(16) __half g_W6 [HID * DFEAT];   // [N,K] fp16
__device__ __align__(16) __half g_W7 [HID * HID];
__device__ __align__(16) __half g_H1 [RN * HID];
__device__ __align__(16) float g_wbT [NCLS * 4 * HID]; // w_bbox transposed [84,1024]
__device__ __align__(16) float g_part[NSPLIT * RN * HID];
__device__ float g_H2[RN * HID];
__device__ float g_cls[RN];
__device__ float g_box[RN];

// ---------------- PTX helpers ------------------------------------------------------
__device__ __forceinline__ uint32_t smem_u32(const void* p) {
    uint32_t a;
    asm("{ .reg .u64 t; cvta.to.shared.u64 t, %1; cvt.u32.u64 %0, t; }" : "=r"(a) : "l"(p));
    return a;
}
__device__ __forceinline__ void cp16(void* sdst, const void* gsrc) {
    uint32_t d = smem_u32(sdst);
    asm volatile("cp.async.cg.shared.global [%0], [%1], 16;" :: "r"(d), "l"(gsrc) : "memory");
}
__device__ __forceinline__ void cp_commit() {
    asm volatile("cp.async.commit_group;" ::: "memory");
}
template <int N>
__device__ __forceinline__ void cp_wait() {
    asm volatile("cp.async.wait_group %0;" :: "n"(N) : "memory");
}
__device__ __forceinline__ void ldsm4(uint32_t* r, uint32_t addr) {
    asm volatile("ldmatrix.sync.aligned.m8n8.x4.shared.b16 {%0,%1,%2,%3}, [%4];"
                 : "=r"(r[0]), "=r"(r[1]), "=r"(r[2]), "=r"(r[3]) : "r"(addr));
}
__device__ __forceinline__ void mma16816(float* c, const uint32_t* a, const uint32_t* b) {
    asm volatile("mma.sync.aligned.m16n8k16.row.col.f32.f16.f16.f32 "
                 "{%0,%1,%2,%3}, {%4,%5,%6,%7}, {%8,%9}, {%0,%1,%2,%3};"
                 : "+f"(c[0]), "+f"(c[1]), "+f"(c[2]), "+f"(c[3])
                 : "r"(a[0]), "r"(a[1]), "r"(a[2]), "r"(a[3]), "r"(b[0]), "r"(b[1]));
}

// ---------------- ROIAlign: R9 mapping, division-free loop -------------------------
// Thread t covers idx = t, t+512, ... over DFEAT (exactly R9's mapping/addresses);
// (c, bin) tracked incrementally, ph/pw via 49-entry LUTs, row offsets pre-scaled.
__global__ void roi_align_kernel(const float* __restrict__ p2, const float* __restrict__ p3,
                                 const float* __restrict__ p4, const float* __restrict__ p5,
                                 const float* __restrict__ rois, const int* __restrict__ batch_idx)
{
    __shared__ float slx[14], sly[14];
    __shared__ int   sx0[14], sx1[14], sy0[14], sy1[14];  // sy* premultiplied by S
    __shared__ int   svx[14], svy[14];
    __shared__ int   tiy[49], tix[49];                     // bin -> 2*ph, 2*pw

    int r = blockIdx.x;
    float x1 = rois[r*4+0], y1 = rois[r*4+1], x2 = rois[r*4+2], y2 = rois[r*4+3];
    float area = (x2 - x1) * (y2 - y1);
    float lf = floorf(4.0f + log2f(sqrtf(area) / 224.0f + 1e-6f));
    lf = fminf(fmaxf(lf, 2.0f), 5.0f);
    int lvl = (int)lf - 2;
    int S = 56 >> lvl;
    float scale = 0.25f / (float)(1 << lvl);
    const float* feat = (lvl == 0) ? p2 : (lvl == 1) ? p3 : (lvl == 2) ? p4 : p5;
    int b = batch_idx[r];
    const float* img0 = feat + (size_t)b * CCH * S * S;

    float x1s = x1 * scale, y1s = y1 * scale;
    float rw = fmaxf(x2 * scale - x1s, 1.0f);
    float rh = fmaxf(y2 * scale - y1s, 1.0f);

    int t = threadIdx.x;
    if (t < 14) {
        float kk = ((float)t + 0.5f) * 0.5f;
        float xs = x1s + (rw / 7.0f) * kk;
        svx[t] = (xs >= -1.0f && xs <= (float)S) ? 1 : 0;
        float x = fminf(fmaxf(xs, 0.0f), (float)(S - 1));
        float x0f = floorf(x);
        slx[t] = x - x0f;
        sx0[t] = (int)x0f;
        sx1[t] = min((int)x0f + 1, S - 1);

        float ys = y1s + (rh / 7.0f) * kk;
        svy[t] = (ys >= -1.0f && ys <= (float)S) ? 1 : 0;
        float y = fminf(fmaxf(ys, 0.0f), (float)(S - 1));
        float y0f = floorf(y);
        sly[t] = y - y0f;
        sy0[t] = (int)y0f * S;
        sy1[t] = min((int)y0f + 1, S - 1) * S;
    }
    if (t < 49) {
        tiy[t] = 2 * (t / 7);
        tix[t] = 2 * (t - 7 * (t / 7));
    }
    __syncthreads();

    // incremental (c, bin) for idx = t + i*512 ; 512 = 10*49 + 22
    int c   = t / 49;
    int bin = t - c * 49;
    size_t cstep = (size_t)S * S;
    __half* out = g_X + (size_t)r * DFEAT + t;

    while (c < CCH) {
        int iy = tiy[bin], ix = tix[bin];
        const float* img = img0 + (size_t)c * cstep;
        float acc = 0.0f;
        #pragma unroll
        for (int dy = 0; dy < 2; dy++) {
            int iyd = iy + dy;
            if (!svy[iyd]) continue;
            float ly = sly[iyd], hy = 1.0f - ly;
            int y0 = sy0[iyd], y1r = sy1[iyd];
            #pragma unroll
            for (int dx = 0; dx < 2; dx++) {
                int ixd = ix + dx;
                if (!svx[ixd]) continue;
                float lx = slx[ixd], hx = 1.0f - lx;
                int x0 = sx0[ixd], x1i = sx1[ixd];
                acc += img[y0 + x0]  * (hy * hx) + img[y0 + x1i]  * (hy * lx)
                     + img[y1r + x0] * (ly * hx) + img[y1r + x1i] * (ly * lx);
            }
        }
        *out = __float2half(acc * 0.25f);
        out += 512;
        c += 10;
        bin += 22;
        if (bin >= 49) { bin -= 49; c += 1; }
    }
}

// ---------------- transpose to fp16: W[K,N] -> T[N,K] -----------------------------
__global__ void transpose_h(const float* __restrict__ W, __half* __restrict__ T,
                            int K, int N)
{
    __shared__ float tile[32][33];
    int k0 = blockIdx.x * 32, n0 = blockIdx.y * 32;
    int tx = threadIdx.x, ty = threadIdx.y;
    #pragma unroll
    for (int i = 0; i < 4; i++)
        tile[ty + i*8][tx] = W[(size_t)(k0 + ty + i*8) * N + n0 + tx];
    __syncthreads();
    #pragma unroll
    for (int i = 0; i < 4; i++) {
        int n = n0 + ty + i*8;
        int k = k0 + tx;
        T[(size_t)n * K + k] = __float2half(tile[tx][ty + i*8]);
    }
}

// ---------------- w_bbox transpose fp32: wb[1024,84] -> g_wbT[84,1024] ------------
__global__ void transpose_b(const float* __restrict__ wb)
{
    __shared__ float tile[32][33];
    int b = blockIdx.x;                          // 0..95
    int k0 = (b % 32) * 32, c0 = (b / 32) * 32;  // c0 in {0,32,64}
    int tx = threadIdx.x, ty = threadIdx.y;
    #pragma unroll
    for (int i = 0; i < 4; i++) {
        int c = c0 + tx;
        tile[ty + i*8][tx] = (c < NCLS*4) ? wb[(size_t)(k0 + ty + i*8) * (NCLS*4) + c] : 0.0f;
    }
    __syncthreads();
    #pragma unroll
    for (int i = 0; i < 4; i++) {
        int c = c0 + ty + i*8;
        if (c < NCLS*4) g_wbT[(size_t)c * HID + k0 + tx] = tile[tx][ty + i*8];
    }
}

// ---------------- fp16 GEMM on mma.sync (HMMA), split-K, 3-stage -------------------
__global__ __launch_bounds__(256, 2)
void gemmh(const __half* __restrict__ A, const __half* __restrict__ B,
           float* __restrict__ part, int K, int kLen)
{
    extern __shared__ __half sm[];
    int tid = threadIdx.x, wid = tid >> 5, lane = tid & 31;
    int bm = blockIdx.y * BM, bn = blockIdx.x * BN;
    int kOff = blockIdx.z * kLen;
    float* pout = part + (size_t)blockIdx.z * RN * HID;
    int wm = (wid & 3) * 32;
    int wn = (wid >> 2) * 32;

    float acc[2][4][4];
    #pragma unroll
    for (int mt = 0; mt < 2; mt++)
        #pragma unroll
        for (int nt = 0; nt < 4; nt++)
            #pragma unroll
            for (int i = 0; i < 4; i++) acc[mt][nt][i] = 0.0f;

    int nc = kLen / BK;

    auto load_stage = [&](int c, int s) {
        __half* st = sm + s * STAGE_ELEMS;
        int k0 = kOff + c * BK;
        #pragma unroll
        for (int j = 0; j < 4; j++) {
            int i = tid + j * 256;
            int row = i >> 3, seg = i & 7;
            cp16(&st[row * ASTRIDE + seg * 8], &A[(size_t)(bm + row) * K + k0 + seg * 8]);
        }
        #pragma unroll
        for (int j = 0; j < 2; j++) {
            int i = tid + j * 256;
            int row = i >> 3, seg = i & 7;
            cp16(&st[A_ELEMS + row * ASTRIDE + seg * 8], &B[(size_t)(bn + row) * K + k0 + seg * 8]);
        }
        cp_commit();
    };

    load_stage(0, 0);
    load_stage(1, 1);

    for (int c = 0; c < nc; c++) {
        if (c + 1 < nc) cp_wait<1>(); else cp_wait<0>();
        __syncthreads();
        if (c + 2 < nc) load_stage(c + 2, (c + 2) % NST);

        __half* st = sm + (c % NST) * STAGE_ELEMS;
        uint32_t sA = smem_u32(st);
        #pragma unroll
        for (int ks = 0; ks < 4; ks++) {
            int kc = ks * 16;
            uint32_t ah[2][4], bb[4][2];
            #pragma unroll
            for (int mt = 0; mt < 2; mt++) {
                int row = wm + mt * 16 + (lane & 15);
                int col = kc + ((lane >> 4) << 3);
                ldsm4(ah[mt], sA + (uint32_t)(row * ASTRIDE + col) * 2);
            }
            #pragma unroll
            for (int p = 0; p < 2; p++) {
                int rown = wn + p * 16 + ((lane & 16) >> 1) + (lane & 7);
                int col = kc + (lane & 8);
                uint32_t r4[4];
                ldsm4(r4, sA + A_ELEMS * 2 + (uint32_t)(rown * ASTRIDE + col) * 2);
                bb[2*p][0] = r4[0]; bb[2*p][1] = r4[1];
                bb[2*p+1][0] = r4[2]; bb[2*p+1][1] = r4[3];
            }
            #pragma unroll
            for (int mt = 0; mt < 2; mt++)
                #pragma unroll
                for (int nt = 0; nt < 4; nt++)
                    mma16816(acc[mt][nt], ah[mt], bb[nt]);
        }
    }

    int lrow = lane >> 2, lcol = (lane & 3) * 2;
    #pragma unroll
    for (int mt = 0; mt < 2; mt++) {
        #pragma unroll
        for (int nt = 0; nt < 4; nt++) {
            int col = bn + wn + nt * 8 + lcol;
            #pragma unroll
            for (int half = 0; half < 2; half++) {
                int row = bm + wm + mt * 16 + lrow + half * 8;
                float2 v;
                v.x = acc[mt][nt][half * 2 + 0];
                v.y = acc[mt][nt][half * 2 + 1];
                *(float2*)&pout[(size_t)row * HID + col] = v;
            }
        }
    }
}

// ---------------- combine split-K partials + bias + relu --------------------------
__global__ void combine_kernel(const float* __restrict__ part, const float* __restrict__ bias,
                               float* __restrict__ outf, __half* __restrict__ Oh, int mode)
{
    int idx = blockIdx.x * blockDim.x + threadIdx.x;
    int col = idx & (HID - 1);
    float v = part[idx] + part[RN * HID + idx] + bias[col];
    v = fmaxf(v, 0.0f);
    if (mode == 0) outf[idx] = v;
    else           Oh[idx] = __float2half(v);
}

// ---------------- head: smem-staged w_cls, coalesced wbT, per-roi losses ----------
__global__ void head_loss_kernel(const float* __restrict__ H2,
                                 const float* __restrict__ w_cls, const float* __restrict__ b_cls,
                                 const float* __restrict__ b_bbox,
                                 const int* __restrict__ labels, const float* __restrict__ regt)
{
    extern __shared__ float swc[];      // [1024*21]
    int t = threadIdx.x, warp = t >> 5, lane = t & 31;
    for (int i = t; i < HID * NCLS; i += 256) swc[i] = w_cls[i];
    __syncthreads();

    #pragma unroll
    for (int q = 0; q < 2; q++) {
        int r = blockIdx.x * 16 + warp * 2 + q;
        int label = labels[r];

        float x[32];
        #pragma unroll
        for (int i = 0; i < 32; i++) x[i] = H2[(size_t)r * HID + lane + 32 * i];

        float lg[NCLS];
        #pragma unroll
        for (int j = 0; j < NCLS; j++) {
            float s = 0.0f;
            #pragma unroll
            for (int i = 0; i < 32; i++) s += x[i] * swc[(lane + 32 * i) * NCLS + j];
            #pragma unroll
            for (int o = 16; o > 0; o >>= 1) s += __shfl_xor_sync(0xffffffffu, s, o);
            lg[j] = s + b_cls[j];
        }

        float sel[4];
        #pragma unroll
        for (int i4 = 0; i4 < 4; i4++) {
            const float* wrow = g_wbT + (size_t)(label * 4 + i4) * HID;
            float s = 0.0f;
            #pragma unroll
            for (int i = 0; i < 32; i++) s += x[i] * wrow[lane + 32 * i];
            #pragma unroll
            for (int o = 16; o > 0; o >>= 1) s += __shfl_xor_sync(0xffffffffu, s, o);
            sel[i4] = s + b_bbox[label * 4 + i4];
        }

        if (lane == 0) {
            float m = -1e30f;
            #pragma unroll
            for (int j = 0; j < NCLS; j++) m = fmaxf(m, lg[j]);
            float se = 0.0f;
            #pragma unroll
            for (int j = 0; j < NCLS; j++) se += expf(lg[j] - m);
            float ce = logf(se) + m - lg[label];
            float pt = expf(-ce);
            float fw = (1.0f - pt) * (1.0f - pt);
            float aw = (label > 0) ? 0.25f : 0.75f;
            g_cls[r] = fw * aw * ce;

            float bl = 0.0f;
            #pragma unroll
            for (int i4 = 0; i4 < 4; i4++) {
                float d = sel[i4] - regt[r * 4 + i4];
                float ad = fabsf(d);
                bl += (ad < BETA) ? 0.5f * d * d / BETA : ad - 0.5f * BETA;
            }
            g_box[r] = (label > 0) ? bl : 0.0f;
        }
    }
}

// ---------------- deterministic final reduction -----------------------------------
__global__ void reduce_kernel(float* __restrict__ out)
{
    __shared__ float s1[RN];
    __shared__ float s2[RN];
    int t = threadIdx.x;
    s1[t] = g_cls[t];
    s2[t] = g_box[t];
    __syncthreads();
    for (int o = RN / 2; o > 0; o >>= 1) {
        if (t < o) { s1[t] += s1[t + o]; s2[t] += s2[t + o]; }
        __syncthreads();
    }
    if (t == 0) {
        out[0] = s1[0] / (float)RN;
        out[1] = s2[0] / (float)RN;
    }
}

// ---------------- launch ----------------------------------------------------------
extern "C" void kernel_launch(void* const* d_in, const int* in_sizes, int n_in,
                              void* d_out, int out_size)
{
    const float* p2     = (const float*)d_in[0];
    const float* p3     = (const float*)d_in[1];
    const float* p4     = (const float*)d_in[2];
    const float* p5     = (const float*)d_in[3];
    const float* rois   = (const float*)d_in[4];
    const int*   bidx   = (const int*)  d_in[5];
    const int*   labels = (const int*)  d_in[6];
    const float* regt   = (const float*)d_in[7];
    const float* w_fc6  = (const float*)d_in[8];
    const float* b_fc6  = (const float*)d_in[9];
    const float* w_fc7  = (const float*)d_in[10];
    const float* b_fc7  = (const float*)d_in[11];
    const float* w_cls  = (const float*)d_in[12];
    const float* b_cls  = (const float*)d_in[13];
    const float* w_bbox = (const float*)d_in[14];
    const float* b_bbox = (const float*)d_in[15];

    __half *Xp, *W6p, *W7p, *H1p;
    float *H2p, *Pp;
    cudaGetSymbolAddress((void**)&Xp,  g_X);
    cudaGetSymbolAddress((void**)&W6p, g_W6);
    cudaGetSymbolAddress((void**)&W7p, g_W7);
    cudaGetSymbolAddress((void**)&H1p, g_H1);
    cudaGetSymbolAddress((void**)&H2p, g_H2);
    cudaGetSymbolAddress((void**)&Pp,  g_part);

    cudaFuncSetAttribute(gemmh, cudaFuncAttributeMaxDynamicSharedMemorySize, GSMEM_BYTES);
    cudaFuncSetAttribute(head_loss_kernel, cudaFuncAttributeMaxDynamicSharedMemorySize,
                         HID * NCLS * (int)sizeof(float));

    // 1) weight transposes first (streaming traffic done before roi's L2 window)
    transpose_h<<<dim3(DFEAT / 32, HID / 32), dim3(32, 8)>>>(w_fc6, W6p, DFEAT, HID);
    transpose_h<<<dim3(HID / 32, HID / 32),   dim3(32, 8)>>>(w_fc7, W7p, HID, HID);
    transpose_b<<<96, dim3(32, 8)>>>(w_bbox);

    // 2) ROIAlign + flatten -> g_X fp16 [1024, 18816]
    roi_align_kernel<<<RN, 512>>>(p2, p3, p4, p5, rois, bidx);

    // 3) fc6 split-K=2 -> combine -> H1 fp16
    dim3 grid(HID / BN, RN / BM, NSPLIT);
    gemmh<<<grid, 256, GSMEM_BYTES>>>(Xp, W6p, Pp, DFEAT, DFEAT / NSPLIT);
    combine_kernel<<<RN * HID / 256, 256>>>(Pp, b_fc6, nullptr, H1p, 1);

    // 4) fc7 split-K=2 -> H2 fp32
    gemmh<<<grid, 256, GSMEM_BYTES>>>(H1p, W7p, Pp, HID, HID / NSPLIT);
    combine_kernel<<<RN * HID / 256, 256>>>(Pp, b_fc7, H2p, nullptr, 0);

    // 5) heads + per-roi losses
    head_loss_kernel<<<64, 256, HID * NCLS * sizeof(float)>>>(H2p, w_cls, b_cls,
                                                              b_bbox, labels, regt);

    // 6) deterministic reduction -> out[0..1]
    reduce_kernel<<<1, RN>>>((float*)d_out);
}